// round 15
// baseline (speedup 1.0000x reference)
#include <cuda_runtime.h>
#include <cuda_bf16.h>
#include <math.h>
#include <cstdint>

// Problem constants
#define B_ 2
#define N_ 2048
#define C_ 768
#define H_ 12
#define DH_ 64
#define SCALE_ 0.125f
#define THREEC_ (3 * C_)        // 2304
#define ROWS_ (B_ * N_)         // 4096

// ---------------------------------------------------------------------------
// Scratch (static __device__ globals — no allocation allowed)
// ---------------------------------------------------------------------------
__device__ __nv_bfloat16   g_qkvh[ROWS_ * THREEC_];      // qkv split hi
__device__ __nv_bfloat16   g_qkvl[ROWS_ * THREEC_];      // qkv split lo
__device__ __nv_bfloat16   g_xh[ROWS_ * C_];
__device__ __nv_bfloat16   g_xl[ROWS_ * C_];
__device__ __nv_bfloat16   g_wqkvTh[THREEC_ * C_];
__device__ __nv_bfloat16   g_wqkvTl[THREEC_ * C_];
__device__ __nv_bfloat16   g_wprojTh[C_ * C_];
__device__ __nv_bfloat16   g_wprojTl[C_ * C_];
__device__ __nv_bfloat16   g_atth[ROWS_ * C_];
__device__ __nv_bfloat16   g_attl[ROWS_ * C_];

// ---------------------------------------------------------------------------
// Helpers (baseline PTX only)
// ---------------------------------------------------------------------------
__device__ __forceinline__ uint32_t smem_to_u32(const void* smem_ptr) {
    uint32_t addr;
    asm("{ .reg .u64 tmp; cvta.to.shared.u64 tmp, %1; cvt.u32.u64 %0, tmp; }"
        : "=r"(addr) : "l"(smem_ptr));
    return addr;
}

__device__ __forceinline__ void ldsm_x4(uint32_t& r0, uint32_t& r1,
                                        uint32_t& r2, uint32_t& r3, uint32_t addr) {
    asm volatile("ldmatrix.sync.aligned.m8n8.x4.shared.b16 {%0,%1,%2,%3}, [%4];"
                 : "=r"(r0), "=r"(r1), "=r"(r2), "=r"(r3) : "r"(addr));
}

__device__ __forceinline__ void ldsm_x4_t(uint32_t& r0, uint32_t& r1,
                                          uint32_t& r2, uint32_t& r3, uint32_t addr) {
    asm volatile("ldmatrix.sync.aligned.m8n8.x4.trans.shared.b16 {%0,%1,%2,%3}, [%4];"
                 : "=r"(r0), "=r"(r1), "=r"(r2), "=r"(r3) : "r"(addr));
}

__device__ __forceinline__ void mma_bf16(float* c, const uint32_t* a, const uint32_t* b) {
    asm volatile(
        "mma.sync.aligned.m16n8k16.row.col.f32.bf16.bf16.f32 "
        "{%0,%1,%2,%3}, {%4,%5,%6,%7}, {%8,%9}, {%0,%1,%2,%3};"
        : "+f"(c[0]), "+f"(c[1]), "+f"(c[2]), "+f"(c[3])
        : "r"(a[0]), "r"(a[1]), "r"(a[2]), "r"(a[3]), "r"(b[0]), "r"(b[1]));
}

#define CP_ASYNC16(saddr, gptr) \
    asm volatile("cp.async.cg.shared.global [%0], [%1], 16;" \
                 :: "r"(saddr), "l"(gptr) : "memory")
#define CP_COMMIT() asm volatile("cp.async.commit_group;" ::: "memory")
#define CP_WAIT0()  asm volatile("cp.async.wait_group 0;" ::: "memory")

// ---------------------------------------------------------------------------
// Prep 1: fp32 -> split bf16 (hi + lo)
// ---------------------------------------------------------------------------
__global__ void split_kernel(const float* __restrict__ src,
                             __nv_bfloat16* __restrict__ dh,
                             __nv_bfloat16* __restrict__ dl, int n)
{
    int i = blockIdx.x * blockDim.x + threadIdx.x;
    if (2 * i >= n) return;
    float2 v = *(const float2*)(src + 2 * i);
    __nv_bfloat16 h0 = __float2bfloat16(v.x);
    __nv_bfloat16 h1 = __float2bfloat16(v.y);
    __nv_bfloat16 l0 = __float2bfloat16(v.x - __bfloat162float(h0));
    __nv_bfloat16 l1 = __float2bfloat16(v.y - __bfloat162float(h1));
    *(__nv_bfloat162*)(dh + 2 * i) = __nv_bfloat162(h0, h1);
    *(__nv_bfloat162*)(dl + 2 * i) = __nv_bfloat162(l0, l1);
}

// ---------------------------------------------------------------------------
// Prep 2: transpose + split: src[K,N] fp32 -> dst[N,K] split bf16
// ---------------------------------------------------------------------------
__global__ void transpose_split_kernel(const float* __restrict__ src,
                                       __nv_bfloat16* __restrict__ dh,
                                       __nv_bfloat16* __restrict__ dl,
                                       int K, int N)
{
    __shared__ float tile[32][33];
    int n0 = blockIdx.x * 32;
    int k0 = blockIdx.y * 32;
    #pragma unroll
    for (int i = 0; i < 4; ++i) {
        int k = k0 + threadIdx.y + i * 8;
        tile[threadIdx.y + i * 8][threadIdx.x] = src[(size_t)k * N + n0 + threadIdx.x];
    }
    __syncthreads();
    #pragma unroll
    for (int i = 0; i < 4; ++i) {
        int n = n0 + threadIdx.y + i * 8;
        int k = k0 + threadIdx.x;
        float v = tile[threadIdx.x][threadIdx.y + i * 8];
        __nv_bfloat16 h = __float2bfloat16(v);
        dh[(size_t)n * K + k] = h;
        dl[(size_t)n * K + k] = __float2bfloat16(v - __bfloat162float(h));
    }
}

// ---------------------------------------------------------------------------
// Split-precision bf16 GEMM on mma.sync (m16n8k16), cp.async double-buffered.
// Templated on NT (output-tile N width): 128 or 64. CTA tile = 128 x NT.
// If Couth != nullptr: epilogue writes split bf16 (hi/lo); else fp32 (+bias).
// ---------------------------------------------------------------------------
#define BKG 32
#define SPITCH 40
#define GA_TILE (128 * SPITCH * 2)          // 10240 B (A tile, fixed 128 rows)

template <int NT>
__global__ __launch_bounds__(256) void gemm_mma_kernel(
    const __nv_bfloat16* __restrict__ Ah, const __nv_bfloat16* __restrict__ Al,
    const __nv_bfloat16* __restrict__ Bh, const __nv_bfloat16* __restrict__ Bl,
    const float* __restrict__ bias, float* __restrict__ Cout,
    __nv_bfloat16* __restrict__ Couth, __nv_bfloat16* __restrict__ Coutl,
    int M, int Nout, int K)
{
    constexpr int GB_TILE  = NT * SPITCH * 2;              // B tile bytes
    constexpr int G_STAGE  = 2 * GA_TILE + 2 * GB_TILE;    // per-stage bytes
    constexpr int NFR      = NT / 16;                      // B frags per warp
    constexpr int NP       = NT / 32;                      // ldsm iters for B

    extern __shared__ char gsm[];
    const uint32_t sbase = smem_to_u32(gsm);

    const int t    = threadIdx.x;
    const int wid  = t >> 5;
    const int lid  = t & 31;
    const int row0 = blockIdx.y * 128;
    const int col0 = blockIdx.x * NT;
    const int m0w  = (wid & 3) * 32;
    const int n0w  = (wid >> 2) * (NT / 2);
    const int gid  = lid >> 2;
    const int tig  = lid & 3;

    const int sub   = lid >> 3;
    const int rr    = lid & 7;
    const int a_row = m0w + (sub & 1) * 8 + rr;
    const int a_kof = (sub >> 1) * 8;
    const int b_row = n0w + (sub >> 1) * 8 + rr;
    const int b_kof = (sub & 1) * 8;

    float acc[2][NFR][4];
    #pragma unroll
    for (int mt = 0; mt < 2; ++mt)
        #pragma unroll
        for (int nt = 0; nt < NFR; ++nt)
            #pragma unroll
            for (int i = 0; i < 4; ++i) acc[mt][nt][i] = 0.f;

    auto issue = [&](int ch, int stage) {
        const int kc = ch * BKG;
        const uint32_t sb = sbase + stage * G_STAGE;
        #pragma unroll
        for (int it = 0; it < 2; ++it) {          // A tiles (128 rows)
            const int idx = it * 256 + t;
            const int r   = idx >> 2;
            const int c   = idx & 3;
            const size_t ga = (size_t)(row0 + r) * K + kc + c * 8;
            const uint32_t so = sb + (uint32_t)(r * SPITCH + c * 8) * 2;
            CP_ASYNC16(so,           Ah + ga);
            CP_ASYNC16(so + GA_TILE, Al + ga);
        }
        #pragma unroll
        for (int it = 0; it < NT / 64; ++it) {    // B tiles (NT rows)
            const int idx = it * 256 + t;
            const int r   = idx >> 2;
            const int c   = idx & 3;
            const size_t gb = (size_t)(col0 + r) * K + kc + c * 8;
            const uint32_t so = sb + 2 * GA_TILE + (uint32_t)(r * SPITCH + c * 8) * 2;
            CP_ASYNC16(so,           Bh + gb);
            CP_ASYNC16(so + GB_TILE, Bl + gb);
        }
        CP_COMMIT();
    };

    const int nchunk = K / BKG;
    issue(0, 0);

    for (int ch = 0; ch < nchunk; ++ch) {
        CP_WAIT0();
        __syncthreads();
        if (ch + 1 < nchunk) issue(ch + 1, (ch + 1) & 1);

        const uint32_t sb  = sbase + (ch & 1) * G_STAGE;
        const uint32_t uAh = sb;
        const uint32_t uAl = sb + GA_TILE;
        const uint32_t uBh = sb + 2 * GA_TILE;
        const uint32_t uBl = sb + 2 * GA_TILE + GB_TILE;

        #pragma unroll
        for (int ks = 0; ks < 2; ++ks) {
            uint32_t ah[2][4], al[2][4], bh[NFR][2], bl[NFR][2];
            #pragma unroll
            for (int mt = 0; mt < 2; ++mt) {
                const uint32_t off = ((a_row + mt * 16) * SPITCH + ks * 16 + a_kof) * 2;
                ldsm_x4(ah[mt][0], ah[mt][1], ah[mt][2], ah[mt][3], uAh + off);
                ldsm_x4(al[mt][0], al[mt][1], al[mt][2], al[mt][3], uAl + off);
            }
            #pragma unroll
            for (int p = 0; p < NP; ++p) {
                const uint32_t off = ((b_row + p * 16) * SPITCH + ks * 16 + b_kof) * 2;
                uint32_t r0, r1, r2, r3;
                ldsm_x4(r0, r1, r2, r3, uBh + off);
                bh[p * 2][0] = r0; bh[p * 2][1] = r1;
                bh[p * 2 + 1][0] = r2; bh[p * 2 + 1][1] = r3;
                ldsm_x4(r0, r1, r2, r3, uBl + off);
                bl[p * 2][0] = r0; bl[p * 2][1] = r1;
                bl[p * 2 + 1][0] = r2; bl[p * 2 + 1][1] = r3;
            }
            // term-outer order: all hh, then hl, then lh (scheduler freedom)
            #pragma unroll
            for (int mt = 0; mt < 2; ++mt)
                #pragma unroll
                for (int nt = 0; nt < NFR; ++nt)
                    mma_bf16(acc[mt][nt], ah[mt], bh[nt]);
            #pragma unroll
            for (int mt = 0; mt < 2; ++mt)
                #pragma unroll
                for (int nt = 0; nt < NFR; ++nt)
                    mma_bf16(acc[mt][nt], ah[mt], bl[nt]);
            #pragma unroll
            for (int mt = 0; mt < 2; ++mt)
                #pragma unroll
                for (int nt = 0; nt < NFR; ++nt)
                    mma_bf16(acc[mt][nt], al[mt], bh[nt]);
        }
        // no bottom barrier: next iteration's CP_WAIT0 + __syncthreads orders
        // all readers of this stage before its buffer is re-issued (ch+2).
    }

    // Epilogue
    if (Couth) {
        #pragma unroll
        for (int mt = 0; mt < 2; ++mt)
            #pragma unroll
            for (int nt = 0; nt < NFR; ++nt) {
                const int rowg = row0 + m0w + mt * 16 + gid;
                const int colg = col0 + n0w + nt * 8 + tig * 2;
                const float o0 = acc[mt][nt][0], o1 = acc[mt][nt][1];
                const float o2 = acc[mt][nt][2], o3 = acc[mt][nt][3];
                __nv_bfloat162 h01 = __floats2bfloat162_rn(o0, o1);
                __nv_bfloat162 h23 = __floats2bfloat162_rn(o2, o3);
                float2 f01 = __bfloat1622float2(h01);
                float2 f23 = __bfloat1622float2(h23);
                __nv_bfloat162 l01 = __floats2bfloat162_rn(o0 - f01.x, o1 - f01.y);
                __nv_bfloat162 l23 = __floats2bfloat162_rn(o2 - f23.x, o3 - f23.y);
                const size_t g0 = (size_t)rowg * Nout + colg;
                const size_t g1 = (size_t)(rowg + 8) * Nout + colg;
                *(__nv_bfloat162*)(Couth + g0) = h01;
                *(__nv_bfloat162*)(Coutl + g0) = l01;
                *(__nv_bfloat162*)(Couth + g1) = h23;
                *(__nv_bfloat162*)(Coutl + g1) = l23;
            }
    } else {
        #pragma unroll
        for (int mt = 0; mt < 2; ++mt)
            #pragma unroll
            for (int nt = 0; nt < NFR; ++nt) {
                const int rowg = row0 + m0w + mt * 16 + gid;
                const int colg = col0 + n0w + nt * 8 + tig * 2;
                float2 v0 = make_float2(acc[mt][nt][0], acc[mt][nt][1]);
                float2 v1 = make_float2(acc[mt][nt][2], acc[mt][nt][3]);
                if (bias) {
                    const float b0 = bias[colg], b1 = bias[colg + 1];
                    v0.x += b0; v0.y += b1;
                    v1.x += b0; v1.y += b1;
                }
                *(float2*)(Cout + (size_t)rowg * Nout + colg) = v0;
                *(float2*)(Cout + (size_t)(rowg + 8) * Nout + colg) = v1;
            }
    }
}

#define G_SMEM_128 (2 * (2 * GA_TILE + 2 * (128 * SPITCH * 2)))   // 81920
#define G_SMEM_64  (2 * (2 * GA_TILE + 2 * (64 * SPITCH * 2)))    // 61440

// ---------------------------------------------------------------------------
// Flash attention on mma.sync, split-3 precision, cp.async double-buffered K/V.
// CTA: 128 queries x one (b,h); 256 threads = 8 warps (4 over M x 2 over keys).
// ---------------------------------------------------------------------------
#define FPITCH 72
#define FTILE_B (128 * FPITCH * 2)       // 18432 B
#define OFF_QH 0
#define OFF_QL FTILE_B
#define OFF_KV (2 * FTILE_B)             // 36864
#define AKV_STAGE (4 * FTILE_B)          // 73728 (KH,KL,VH,VL)
#define OFF_L (OFF_KV + 2 * AKV_STAGE)   // 184320
#define ATTN_SMEM (OFF_L + 512)          // 184832
#define OPITCH 66

__global__ __launch_bounds__(256) void flash_attn_kernel(
    const __nv_bfloat16* __restrict__ qkvh, const __nv_bfloat16* __restrict__ qkvl,
    const float* __restrict__ gate,
    __nv_bfloat16* __restrict__ atth, __nv_bfloat16* __restrict__ attl)
{
    extern __shared__ char sm[];
    __nv_bfloat16* Qh = (__nv_bfloat16*)(sm + OFF_QH);
    __nv_bfloat16* Ql = (__nv_bfloat16*)(sm + OFF_QL);
    float* l_buf = (float*)(sm + OFF_L);
    const uint32_t sbase = smem_to_u32(sm);

    const int t   = threadIdx.x;
    const int wid = t >> 5;
    const int lid = t & 31;
    const int qt  = blockIdx.x;
    const int bh  = blockIdx.y;
    const int b   = bh / H_;
    const int h   = bh % H_;

    const int m0w = (wid & 3) * 32;
    const int n0w = (wid >> 2) * 64;
    const int gid = lid >> 2;
    const int tig = lid & 3;
    const int sub = lid >> 3;
    const int rr  = lid & 7;
    const int a_row = m0w + (sub & 1) * 8 + rr;
    const int a_kof = (sub >> 1) * 8;
    const int b_row = n0w + (sub >> 1) * 8 + rr;
    const int b_kof = (sub & 1) * 8;
    const int v_row = (sub & 1) * 8 + rr;
    const int v_col = (sub >> 1) * 8;

    const uint32_t uQh = sbase + OFF_QH, uQl = sbase + OFF_QL;
    const float gv = __ldg(&gate[h]);

    if (t < 128) l_buf[t] = 0.f;

    // ---- K/V async loader ----
    const size_t kvroot = (size_t)(b * N_) * THREEC_ + C_ + h * DH_;
    auto issue_kv = [&](int kt, int stage) {
        const size_t kbase = kvroot + (size_t)(kt * 128) * THREEC_;
        const uint32_t sb = sbase + OFF_KV + stage * AKV_STAGE;
        #pragma unroll
        for (int i = 0; i < 4; ++i) {
            const int idx = i * 256 + t;
            const int r   = idx >> 3;
            const int c8  = idx & 7;
            const size_t go = kbase + (size_t)r * THREEC_ + c8 * 8;
            const uint32_t so = sb + (uint32_t)(r * FPITCH + c8 * 8) * 2;
            CP_ASYNC16(so,               qkvh + go);
            CP_ASYNC16(so + FTILE_B,     qkvl + go);
            CP_ASYNC16(so + 2 * FTILE_B, qkvh + go + C_);
            CP_ASYNC16(so + 3 * FTILE_B, qkvl + go + C_);
        }
        CP_COMMIT();
    };

    // ---- Load Q tile (scaled by 0.125, exact in bf16) ----
    {
        const __nv_bfloat162 sc = __floats2bfloat162_rn(SCALE_, SCALE_);
        const size_t qbase = (size_t)(b * N_ + qt * 128) * THREEC_ + h * DH_;
        #pragma unroll
        for (int i = 0; i < 4; ++i) {
            const int idx = i * 256 + t;
            const int r   = idx >> 3;
            const int c8  = idx & 7;
            const size_t go = qbase + (size_t)r * THREEC_ + c8 * 8;
            union { int4 v; __nv_bfloat162 e[4]; } uh, ul;
            uh.v = *(const int4*)(qkvh + go);
            ul.v = *(const int4*)(qkvl + go);
            #pragma unroll
            for (int j = 0; j < 4; ++j) {
                uh.e[j] = __hmul2(uh.e[j], sc);
                ul.e[j] = __hmul2(ul.e[j], sc);
            }
            *(int4*)&Qh[r * FPITCH + c8 * 8] = uh.v;
            *(int4*)&Ql[r * FPITCH + c8 * 8] = ul.v;
        }
    }

    float oacc[2][8][4];
    #pragma unroll
    for (int mt = 0; mt < 2; ++mt)
        #pragma unroll
        for (int nt = 0; nt < 8; ++nt)
            #pragma unroll
            for (int i = 0; i < 4; ++i) oacc[mt][nt][i] = 0.f;
    float lsum[2][2] = {{0.f, 0.f}, {0.f, 0.f}};

    issue_kv(0, 0);

    for (int kt = 0; kt < N_ / 128; ++kt) {
        CP_WAIT0();
        __syncthreads();
        if (kt + 1 < N_ / 128) issue_kv(kt + 1, (kt + 1) & 1);

        const uint32_t sb  = sbase + OFF_KV + (kt & 1) * AKV_STAGE;
        const uint32_t uKh = sb;
        const uint32_t uKl = sb + FTILE_B;
        const uint32_t uVh = sb + 2 * FTILE_B;
        const uint32_t uVl = sb + 3 * FTILE_B;

        // ---- S = Q K^T (split-3, term-outer per ks) ----
        float sacc[2][8][4];
        #pragma unroll
        for (int mt = 0; mt < 2; ++mt)
            #pragma unroll
            for (int nt = 0; nt < 8; ++nt)
                #pragma unroll
                for (int i = 0; i < 4; ++i) sacc[mt][nt][i] = 0.f;

        #pragma unroll
        for (int ks = 0; ks < 4; ++ks) {
            uint32_t ah[2][4], al[2][4], kbh[8][2], kbl[8][2];
            #pragma unroll
            for (int mt = 0; mt < 2; ++mt) {
                const uint32_t off = ((a_row + mt * 16) * FPITCH + ks * 16 + a_kof) * 2;
                ldsm_x4(ah[mt][0], ah[mt][1], ah[mt][2], ah[mt][3], uQh + off);
                ldsm_x4(al[mt][0], al[mt][1], al[mt][2], al[mt][3], uQl + off);
            }
            #pragma unroll
            for (int p = 0; p < 4; ++p) {
                const uint32_t off = ((b_row + p * 16) * FPITCH + ks * 16 + b_kof) * 2;
                uint32_t r0, r1, r2, r3;
                ldsm_x4(r0, r1, r2, r3, uKh + off);
                kbh[p * 2][0] = r0; kbh[p * 2][1] = r1;
                kbh[p * 2 + 1][0] = r2; kbh[p * 2 + 1][1] = r3;
                ldsm_x4(r0, r1, r2, r3, uKl + off);
                kbl[p * 2][0] = r0; kbl[p * 2][1] = r1;
                kbl[p * 2 + 1][0] = r2; kbl[p * 2 + 1][1] = r3;
            }
            #pragma unroll
            for (int mt = 0; mt < 2; ++mt)
                #pragma unroll
                for (int nt = 0; nt < 8; ++nt)
                    mma_bf16(sacc[mt][nt], ah[mt], kbh[nt]);
            #pragma unroll
            for (int mt = 0; mt < 2; ++mt)
                #pragma unroll
                for (int nt = 0; nt < 8; ++nt)
                    mma_bf16(sacc[mt][nt], ah[mt], kbl[nt]);
            #pragma unroll
            for (int mt = 0; mt < 2; ++mt)
                #pragma unroll
                for (int nt = 0; nt < 8; ++nt)
                    mma_bf16(sacc[mt][nt], al[mt], kbh[nt]);
        }

        // ---- softmax numerators + split P ----
        uint32_t phi01[2][8], phi23[2][8], plo01[2][8], plo23[2][8];
        #pragma unroll
        for (int mt = 0; mt < 2; ++mt)
            #pragma unroll
            for (int nt = 0; nt < 8; ++nt) {
                const float p0 = __expf(sacc[mt][nt][0]);
                const float p1 = __expf(sacc[mt][nt][1]);
                const float p2 = __expf(sacc[mt][nt][2]);
                const float p3 = __expf(sacc[mt][nt][3]);
                lsum[mt][0] += p0 + p1;
                lsum[mt][1] += p2 + p3;
                __nv_bfloat162 h01 = __floats2bfloat162_rn(p0, p1);
                __nv_bfloat162 h23 = __floats2bfloat162_rn(p2, p3);
                float2 f01 = __bfloat1622float2(h01);
                float2 f23 = __bfloat1622float2(h23);
                __nv_bfloat162 l01 = __floats2bfloat162_rn(p0 - f01.x, p1 - f01.y);
                __nv_bfloat162 l23 = __floats2bfloat162_rn(p2 - f23.x, p3 - f23.y);
                phi01[mt][nt] = *(uint32_t*)&h01;
                phi23[mt][nt] = *(uint32_t*)&h23;
                plo01[mt][nt] = *(uint32_t*)&l01;
                plo23[mt][nt] = *(uint32_t*)&l23;
            }

        // ---- O += P V (split-3) ----
        #pragma unroll
        for (int ks = 0; ks < 4; ++ks) {
            uint32_t vbh[8][2], vbl[8][2];
            #pragma unroll
            for (int dp = 0; dp < 4; ++dp) {
                const uint32_t off = ((n0w + ks * 16 + v_row) * FPITCH + dp * 16 + v_col) * 2;
                uint32_t r0, r1, r2, r3;
                ldsm_x4_t(r0, r1, r2, r3, uVh + off);
                vbh[dp * 2][0] = r0; vbh[dp * 2][1] = r1;
                vbh[dp * 2 + 1][0] = r2; vbh[dp * 2 + 1][1] = r3;
                ldsm_x4_t(r0, r1, r2, r3, uVl + off);
                vbl[dp * 2][0] = r0; vbl[dp * 2][1] = r1;
                vbl[dp * 2 + 1][0] = r2; vbl[dp * 2 + 1][1] = r3;
            }
            #pragma unroll
            for (int mt = 0; mt < 2; ++mt) {
                const uint32_t pa_h[4] = { phi01[mt][2 * ks], phi23[mt][2 * ks],
                                           phi01[mt][2 * ks + 1], phi23[mt][2 * ks + 1] };
                const uint32_t pa_l[4] = { plo01[mt][2 * ks], plo23[mt][2 * ks],
                                           plo01[mt][2 * ks + 1], plo23[mt][2 * ks + 1] };
                #pragma unroll
                for (int nt = 0; nt < 8; ++nt)
                    mma_bf16(oacc[mt][nt], pa_h, vbh[nt]);
                #pragma unroll
                for (int nt = 0; nt < 8; ++nt)
                    mma_bf16(oacc[mt][nt], pa_h, vbl[nt]);
                #pragma unroll
                for (int nt = 0; nt < 8; ++nt)
                    mma_bf16(oacc[mt][nt], pa_l, vbh[nt]);
            }
        }
        // no bottom barrier: next iteration's CP_WAIT0 + __syncthreads orders
        // all readers of this stage before its buffer is re-issued (kt+2).
    }

    // ---- reduce l across tig quads and warp-pairs ----
    #pragma unroll
    for (int mt = 0; mt < 2; ++mt)
        #pragma unroll
        for (int half = 0; half < 2; ++half) {
            float v = lsum[mt][half];
            v += __shfl_xor_sync(0xFFFFFFFF, v, 1);
            v += __shfl_xor_sync(0xFFFFFFFF, v, 2);
            if (tig == 0)
                atomicAdd(&l_buf[m0w + mt * 16 + gid + half * 8], v);
        }
    __syncthreads();

    // ---- combine O across warp-pairs (staging overlays stage-0 K buffers) ----
    float* Obuf = (float*)(sm + OFF_KV);
    if (wid >= 4) {
        #pragma unroll
        for (int mt = 0; mt < 2; ++mt)
            #pragma unroll
            for (int nt = 0; nt < 8; ++nt) {
                const int row = m0w + mt * 16 + gid;
                const int col = nt * 8 + tig * 2;
                *(float2*)&Obuf[row * OPITCH + col] =
                    make_float2(oacc[mt][nt][0], oacc[mt][nt][1]);
                *(float2*)&Obuf[(row + 8) * OPITCH + col] =
                    make_float2(oacc[mt][nt][2], oacc[mt][nt][3]);
            }
    }
    __syncthreads();
    if (wid < 4) {
        #pragma unroll
        for (int mt = 0; mt < 2; ++mt) {
            const int row0l = m0w + mt * 16 + gid;
            const int row1l = row0l + 8;
            const float inv0 = gv / l_buf[row0l];
            const float inv1 = gv / l_buf[row1l];
            const size_t g0 = (size_t)(b * N_ + qt * 128 + row0l) * C_ + h * DH_;
            const size_t g1 = (size_t)(b * N_ + qt * 128 + row1l) * C_ + h * DH_;
            #pragma unroll
            for (int nt = 0; nt < 8; ++nt) {
                const int col = nt * 8 + tig * 2;
                const float o0 = (oacc[mt][nt][0] + Obuf[row0l * OPITCH + col])     * inv0;
                const float o1 = (oacc[mt][nt][1] + Obuf[row0l * OPITCH + col + 1]) * inv0;
                const float o2 = (oacc[mt][nt][2] + Obuf[row1l * OPITCH + col])     * inv1;
                const float o3 = (oacc[mt][nt][3] + Obuf[row1l * OPITCH + col + 1]) * inv1;
                __nv_bfloat162 h01 = __floats2bfloat162_rn(o0, o1);
                __nv_bfloat162 h23 = __floats2bfloat162_rn(o2, o3);
                float2 f01 = __bfloat1622float2(h01);
                float2 f23 = __bfloat1622float2(h23);
                __nv_bfloat162 l01 = __floats2bfloat162_rn(o0 - f01.x, o1 - f01.y);
                __nv_bfloat162 l23 = __floats2bfloat162_rn(o2 - f23.x, o3 - f23.y);
                *(__nv_bfloat162*)(atth + g0 + col) = h01;
                *(__nv_bfloat162*)(attl + g0 + col) = l01;
                *(__nv_bfloat162*)(atth + g1 + col) = h23;
                *(__nv_bfloat162*)(attl + g1 + col) = l23;
            }
        }
    }
}

// ---------------------------------------------------------------------------
// Launch
// ---------------------------------------------------------------------------
extern "C" void kernel_launch(void* const* d_in, const int* in_sizes, int n_in,
                              void* d_out, int out_size)
{
    const float* x      = (const float*)d_in[0];
    const float* w_qkv  = (const float*)d_in[1];
    const float* gate   = (const float*)d_in[2];
    const float* w_proj = (const float*)d_in[3];
    const float* b_proj = (const float*)d_in[4];
    float* out = (float*)d_out;

    __nv_bfloat16 *qkvh, *qkvl, *xh, *xl, *wqh, *wql, *wph, *wpl, *ath, *atl;
    cudaGetSymbolAddress((void**)&qkvh, g_qkvh);
    cudaGetSymbolAddress((void**)&qkvl, g_qkvl);
    cudaGetSymbolAddress((void**)&xh,   g_xh);
    cudaGetSymbolAddress((void**)&xl,   g_xl);
    cudaGetSymbolAddress((void**)&wqh,  g_wqkvTh);
    cudaGetSymbolAddress((void**)&wql,  g_wqkvTl);
    cudaGetSymbolAddress((void**)&wph,  g_wprojTh);
    cudaGetSymbolAddress((void**)&wpl,  g_wprojTl);
    cudaGetSymbolAddress((void**)&ath,  g_atth);
    cudaGetSymbolAddress((void**)&atl,  g_attl);

    cudaFuncSetAttribute(gemm_mma_kernel<128>,
                         cudaFuncAttributeMaxDynamicSharedMemorySize, G_SMEM_128);
    cudaFuncSetAttribute(gemm_mma_kernel<64>,
                         cudaFuncAttributeMaxDynamicSharedMemorySize, G_SMEM_64);
    cudaFuncSetAttribute(flash_attn_kernel,
                         cudaFuncAttributeMaxDynamicSharedMemorySize, ATTN_SMEM);

    // Prep: split x; transpose+split weights
    {
        int n = ROWS_ * C_;
        split_kernel<<<(n / 2 + 255) / 256, 256>>>(x, xh, xl, n);
        dim3 blk(32, 8);
        dim3 g1(THREEC_ / 32, C_ / 32);
        transpose_split_kernel<<<g1, blk>>>(w_qkv, wqh, wql, C_, THREEC_);
        dim3 g2(C_ / 32, C_ / 32);
        transpose_split_kernel<<<g2, blk>>>(w_proj, wph, wpl, C_, C_);
    }
    // 1) qkv = x @ w_qkv  -> split bf16 written directly by the epilogue
    {
        dim3 grid(THREEC_ / 128, ROWS_ / 128);
        gemm_mma_kernel<128><<<grid, 256, G_SMEM_128>>>(xh, xl, wqh, wql,
                                                        nullptr, nullptr, qkvh, qkvl,
                                                        ROWS_, THREEC_, C_);
    }
    // 2) flash attention + gate -> split bf16
    {
        dim3 grid(N_ / 128, B_ * H_);
        flash_attn_kernel<<<grid, 256, ATTN_SMEM>>>(qkvh, qkvl, gate, ath, atl);
    }
    // 3) out = att @ w_proj + b_proj  (fp32 epilogue, 128x64 tiles for tail)
    {
        dim3 grid(C_ / 64, ROWS_ / 128);
        gemm_mma_kernel<64><<<grid, 256, G_SMEM_64>>>(ath, atl, wph, wpl,
                                                      b_proj, out, nullptr, nullptr,
                                                      ROWS_, C_, C_);
    }
}

// round 16
// speedup vs baseline: 1.0451x; 1.0451x over previous
#include <cuda_runtime.h>
#include <cuda_bf16.h>
#include <math.h>
#include <cstdint>

// Problem constants
#define B_ 2
#define N_ 2048
#define C_ 768
#define H_ 12
#define DH_ 64
#define SCALE_ 0.125f
#define THREEC_ (3 * C_)        // 2304
#define ROWS_ (B_ * N_)         // 4096

// ---------------------------------------------------------------------------
// Scratch (static __device__ globals — no allocation allowed)
// ---------------------------------------------------------------------------
__device__ __nv_bfloat16   g_qkvh[ROWS_ * THREEC_];      // qkv split hi
__device__ __nv_bfloat16   g_qkvl[ROWS_ * THREEC_];      // qkv split lo
__device__ __nv_bfloat16   g_xh[ROWS_ * C_];
__device__ __nv_bfloat16   g_xl[ROWS_ * C_];
__device__ __nv_bfloat16   g_wqkvTh[THREEC_ * C_];
__device__ __nv_bfloat16   g_wqkvTl[THREEC_ * C_];
__device__ __nv_bfloat16   g_wprojTh[C_ * C_];
__device__ __nv_bfloat16   g_wprojTl[C_ * C_];
__device__ __nv_bfloat16   g_atth[ROWS_ * C_];
__device__ __nv_bfloat16   g_attl[ROWS_ * C_];

// ---------------------------------------------------------------------------
// Helpers (baseline PTX only)
// ---------------------------------------------------------------------------
__device__ __forceinline__ uint32_t smem_to_u32(const void* smem_ptr) {
    uint32_t addr;
    asm("{ .reg .u64 tmp; cvta.to.shared.u64 tmp, %1; cvt.u32.u64 %0, tmp; }"
        : "=r"(addr) : "l"(smem_ptr));
    return addr;
}

__device__ __forceinline__ void ldsm_x4(uint32_t& r0, uint32_t& r1,
                                        uint32_t& r2, uint32_t& r3, uint32_t addr) {
    asm volatile("ldmatrix.sync.aligned.m8n8.x4.shared.b16 {%0,%1,%2,%3}, [%4];"
                 : "=r"(r0), "=r"(r1), "=r"(r2), "=r"(r3) : "r"(addr));
}

__device__ __forceinline__ void ldsm_x4_t(uint32_t& r0, uint32_t& r1,
                                          uint32_t& r2, uint32_t& r3, uint32_t addr) {
    asm volatile("ldmatrix.sync.aligned.m8n8.x4.trans.shared.b16 {%0,%1,%2,%3}, [%4];"
                 : "=r"(r0), "=r"(r1), "=r"(r2), "=r"(r3) : "r"(addr));
}

__device__ __forceinline__ void mma_bf16(float* c, const uint32_t* a, const uint32_t* b) {
    asm volatile(
        "mma.sync.aligned.m16n8k16.row.col.f32.bf16.bf16.f32 "
        "{%0,%1,%2,%3}, {%4,%5,%6,%7}, {%8,%9}, {%0,%1,%2,%3};"
        : "+f"(c[0]), "+f"(c[1]), "+f"(c[2]), "+f"(c[3])
        : "r"(a[0]), "r"(a[1]), "r"(a[2]), "r"(a[3]), "r"(b[0]), "r"(b[1]));
}

#define CP_ASYNC16(saddr, gptr) \
    asm volatile("cp.async.cg.shared.global [%0], [%1], 16;" \
                 :: "r"(saddr), "l"(gptr) : "memory")
#define CP_COMMIT() asm volatile("cp.async.commit_group;" ::: "memory")
#define CP_WAIT0()  asm volatile("cp.async.wait_group 0;" ::: "memory")

// ---------------------------------------------------------------------------
// Prep 1: fp32 -> split bf16 (hi + lo)
// ---------------------------------------------------------------------------
__global__ void split_kernel(const float* __restrict__ src,
                             __nv_bfloat16* __restrict__ dh,
                             __nv_bfloat16* __restrict__ dl, int n)
{
    int i = blockIdx.x * blockDim.x + threadIdx.x;
    if (2 * i >= n) return;
    float2 v = *(const float2*)(src + 2 * i);
    __nv_bfloat16 h0 = __float2bfloat16(v.x);
    __nv_bfloat16 h1 = __float2bfloat16(v.y);
    __nv_bfloat16 l0 = __float2bfloat16(v.x - __bfloat162float(h0));
    __nv_bfloat16 l1 = __float2bfloat16(v.y - __bfloat162float(h1));
    *(__nv_bfloat162*)(dh + 2 * i) = __nv_bfloat162(h0, h1);
    *(__nv_bfloat162*)(dl + 2 * i) = __nv_bfloat162(l0, l1);
}

// ---------------------------------------------------------------------------
// Prep 2: transpose + split: src[K,N] fp32 -> dst[N,K] split bf16
// ---------------------------------------------------------------------------
__global__ void transpose_split_kernel(const float* __restrict__ src,
                                       __nv_bfloat16* __restrict__ dh,
                                       __nv_bfloat16* __restrict__ dl,
                                       int K, int N)
{
    __shared__ float tile[32][33];
    int n0 = blockIdx.x * 32;
    int k0 = blockIdx.y * 32;
    #pragma unroll
    for (int i = 0; i < 4; ++i) {
        int k = k0 + threadIdx.y + i * 8;
        tile[threadIdx.y + i * 8][threadIdx.x] = src[(size_t)k * N + n0 + threadIdx.x];
    }
    __syncthreads();
    #pragma unroll
    for (int i = 0; i < 4; ++i) {
        int n = n0 + threadIdx.y + i * 8;
        int k = k0 + threadIdx.x;
        float v = tile[threadIdx.x][threadIdx.y + i * 8];
        __nv_bfloat16 h = __float2bfloat16(v);
        dh[(size_t)n * K + k] = h;
        dl[(size_t)n * K + k] = __float2bfloat16(v - __bfloat162float(h));
    }
}

// ---------------------------------------------------------------------------
// Split-precision bf16 GEMM on mma.sync (m16n8k16), cp.async double-buffered.
// Templated on NT (output-tile N width): 128 or 64. CTA tile = 128 x NT.
// __launch_bounds__(256, 2) pins 2-CTA/SM residency (regs <= 128).
// Interleaved hh/hl/lh per (mt,nt): fragments die fast, low reg pressure.
// If Couth != nullptr: epilogue writes split bf16 (hi/lo); else fp32 (+bias).
// ---------------------------------------------------------------------------
#define BKG 32
#define SPITCH 40
#define GA_TILE (128 * SPITCH * 2)          // 10240 B (A tile, fixed 128 rows)

template <int NT>
__global__ __launch_bounds__(256, 2) void gemm_mma_kernel(
    const __nv_bfloat16* __restrict__ Ah, const __nv_bfloat16* __restrict__ Al,
    const __nv_bfloat16* __restrict__ Bh, const __nv_bfloat16* __restrict__ Bl,
    const float* __restrict__ bias, float* __restrict__ Cout,
    __nv_bfloat16* __restrict__ Couth, __nv_bfloat16* __restrict__ Coutl,
    int M, int Nout, int K)
{
    constexpr int GB_TILE  = NT * SPITCH * 2;              // B tile bytes
    constexpr int G_STAGE  = 2 * GA_TILE + 2 * GB_TILE;    // per-stage bytes
    constexpr int NFR      = NT / 16;                      // B frags per warp
    constexpr int NP       = NT / 32;                      // ldsm iters for B

    extern __shared__ char gsm[];
    const uint32_t sbase = smem_to_u32(gsm);

    const int t    = threadIdx.x;
    const int wid  = t >> 5;
    const int lid  = t & 31;
    const int row0 = blockIdx.y * 128;
    const int col0 = blockIdx.x * NT;
    const int m0w  = (wid & 3) * 32;
    const int n0w  = (wid >> 2) * (NT / 2);
    const int gid  = lid >> 2;
    const int tig  = lid & 3;

    const int sub   = lid >> 3;
    const int rr    = lid & 7;
    const int a_row = m0w + (sub & 1) * 8 + rr;
    const int a_kof = (sub >> 1) * 8;
    const int b_row = n0w + (sub >> 1) * 8 + rr;
    const int b_kof = (sub & 1) * 8;

    float acc[2][NFR][4];
    #pragma unroll
    for (int mt = 0; mt < 2; ++mt)
        #pragma unroll
        for (int nt = 0; nt < NFR; ++nt)
            #pragma unroll
            for (int i = 0; i < 4; ++i) acc[mt][nt][i] = 0.f;

    auto issue = [&](int ch, int stage) {
        const int kc = ch * BKG;
        const uint32_t sb = sbase + stage * G_STAGE;
        #pragma unroll
        for (int it = 0; it < 2; ++it) {          // A tiles (128 rows)
            const int idx = it * 256 + t;
            const int r   = idx >> 2;
            const int c   = idx & 3;
            const size_t ga = (size_t)(row0 + r) * K + kc + c * 8;
            const uint32_t so = sb + (uint32_t)(r * SPITCH + c * 8) * 2;
            CP_ASYNC16(so,           Ah + ga);
            CP_ASYNC16(so + GA_TILE, Al + ga);
        }
        #pragma unroll
        for (int it = 0; it < NT / 64; ++it) {    // B tiles (NT rows)
            const int idx = it * 256 + t;
            const int r   = idx >> 2;
            const int c   = idx & 3;
            const size_t gb = (size_t)(col0 + r) * K + kc + c * 8;
            const uint32_t so = sb + 2 * GA_TILE + (uint32_t)(r * SPITCH + c * 8) * 2;
            CP_ASYNC16(so,           Bh + gb);
            CP_ASYNC16(so + GB_TILE, Bl + gb);
        }
        CP_COMMIT();
    };

    const int nchunk = K / BKG;
    issue(0, 0);

    for (int ch = 0; ch < nchunk; ++ch) {
        CP_WAIT0();
        __syncthreads();
        if (ch + 1 < nchunk) issue(ch + 1, (ch + 1) & 1);

        const uint32_t sb  = sbase + (ch & 1) * G_STAGE;
        const uint32_t uAh = sb;
        const uint32_t uAl = sb + GA_TILE;
        const uint32_t uBh = sb + 2 * GA_TILE;
        const uint32_t uBl = sb + 2 * GA_TILE + GB_TILE;

        #pragma unroll
        for (int ks = 0; ks < 2; ++ks) {
            uint32_t ah[2][4], al[2][4], bh[NFR][2], bl[NFR][2];
            #pragma unroll
            for (int mt = 0; mt < 2; ++mt) {
                const uint32_t off = ((a_row + mt * 16) * SPITCH + ks * 16 + a_kof) * 2;
                ldsm_x4(ah[mt][0], ah[mt][1], ah[mt][2], ah[mt][3], uAh + off);
                ldsm_x4(al[mt][0], al[mt][1], al[mt][2], al[mt][3], uAl + off);
            }
            #pragma unroll
            for (int p = 0; p < NP; ++p) {
                const uint32_t off = ((b_row + p * 16) * SPITCH + ks * 16 + b_kof) * 2;
                uint32_t r0, r1, r2, r3;
                ldsm_x4(r0, r1, r2, r3, uBh + off);
                bh[p * 2][0] = r0; bh[p * 2][1] = r1;
                bh[p * 2 + 1][0] = r2; bh[p * 2 + 1][1] = r3;
                ldsm_x4(r0, r1, r2, r3, uBl + off);
                bl[p * 2][0] = r0; bl[p * 2][1] = r1;
                bl[p * 2 + 1][0] = r2; bl[p * 2 + 1][1] = r3;
            }
            // interleaved split-3 (Round-12 proven low-reg ordering)
            #pragma unroll
            for (int mt = 0; mt < 2; ++mt)
                #pragma unroll
                for (int nt = 0; nt < NFR; ++nt) {
                    mma_bf16(acc[mt][nt], ah[mt], bh[nt]);
                    mma_bf16(acc[mt][nt], ah[mt], bl[nt]);
                    mma_bf16(acc[mt][nt], al[mt], bh[nt]);
                }
        }
        // no bottom barrier: next iteration's CP_WAIT0 + __syncthreads orders
        // all readers of this stage before its buffer is re-issued (ch+2).
    }

    // Epilogue
    if (Couth) {
        #pragma unroll
        for (int mt = 0; mt < 2; ++mt)
            #pragma unroll
            for (int nt = 0; nt < NFR; ++nt) {
                const int rowg = row0 + m0w + mt * 16 + gid;
                const int colg = col0 + n0w + nt * 8 + tig * 2;
                const float o0 = acc[mt][nt][0], o1 = acc[mt][nt][1];
                const float o2 = acc[mt][nt][2], o3 = acc[mt][nt][3];
                __nv_bfloat162 h01 = __floats2bfloat162_rn(o0, o1);
                __nv_bfloat162 h23 = __floats2bfloat162_rn(o2, o3);
                float2 f01 = __bfloat1622float2(h01);
                float2 f23 = __bfloat1622float2(h23);
                __nv_bfloat162 l01 = __floats2bfloat162_rn(o0 - f01.x, o1 - f01.y);
                __nv_bfloat162 l23 = __floats2bfloat162_rn(o2 - f23.x, o3 - f23.y);
                const size_t g0 = (size_t)rowg * Nout + colg;
                const size_t g1 = (size_t)(rowg + 8) * Nout + colg;
                *(__nv_bfloat162*)(Couth + g0) = h01;
                *(__nv_bfloat162*)(Coutl + g0) = l01;
                *(__nv_bfloat162*)(Couth + g1) = h23;
                *(__nv_bfloat162*)(Coutl + g1) = l23;
            }
    } else {
        #pragma unroll
        for (int mt = 0; mt < 2; ++mt)
            #pragma unroll
            for (int nt = 0; nt < NFR; ++nt) {
                const int rowg = row0 + m0w + mt * 16 + gid;
                const int colg = col0 + n0w + nt * 8 + tig * 2;
                float2 v0 = make_float2(acc[mt][nt][0], acc[mt][nt][1]);
                float2 v1 = make_float2(acc[mt][nt][2], acc[mt][nt][3]);
                if (bias) {
                    const float b0 = bias[colg], b1 = bias[colg + 1];
                    v0.x += b0; v0.y += b1;
                    v1.x += b0; v1.y += b1;
                }
                *(float2*)(Cout + (size_t)rowg * Nout + colg) = v0;
                *(float2*)(Cout + (size_t)(rowg + 8) * Nout + colg) = v1;
            }
    }
}

#define G_SMEM_128 (2 * (2 * GA_TILE + 2 * (128 * SPITCH * 2)))   // 81920
#define G_SMEM_64  (2 * (2 * GA_TILE + 2 * (64 * SPITCH * 2)))    // 61440

// ---------------------------------------------------------------------------
// Flash attention on mma.sync, split-3 precision, cp.async double-buffered K/V.
// CTA: 128 queries x one (b,h); 256 threads = 8 warps (4 over M x 2 over keys).
// ---------------------------------------------------------------------------
#define FPITCH 72
#define FTILE_B (128 * FPITCH * 2)       // 18432 B
#define OFF_QH 0
#define OFF_QL FTILE_B
#define OFF_KV (2 * FTILE_B)             // 36864
#define AKV_STAGE (4 * FTILE_B)          // 73728 (KH,KL,VH,VL)
#define OFF_L (OFF_KV + 2 * AKV_STAGE)   // 184320
#define ATTN_SMEM (OFF_L + 512)          // 184832
#define OPITCH 66

__global__ __launch_bounds__(256) void flash_attn_kernel(
    const __nv_bfloat16* __restrict__ qkvh, const __nv_bfloat16* __restrict__ qkvl,
    const float* __restrict__ gate,
    __nv_bfloat16* __restrict__ atth, __nv_bfloat16* __restrict__ attl)
{
    extern __shared__ char sm[];
    __nv_bfloat16* Qh = (__nv_bfloat16*)(sm + OFF_QH);
    __nv_bfloat16* Ql = (__nv_bfloat16*)(sm + OFF_QL);
    float* l_buf = (float*)(sm + OFF_L);
    const uint32_t sbase = smem_to_u32(sm);

    const int t   = threadIdx.x;
    const int wid = t >> 5;
    const int lid = t & 31;
    const int qt  = blockIdx.x;
    const int bh  = blockIdx.y;
    const int b   = bh / H_;
    const int h   = bh % H_;

    const int m0w = (wid & 3) * 32;
    const int n0w = (wid >> 2) * 64;
    const int gid = lid >> 2;
    const int tig = lid & 3;
    const int sub = lid >> 3;
    const int rr  = lid & 7;
    const int a_row = m0w + (sub & 1) * 8 + rr;
    const int a_kof = (sub >> 1) * 8;
    const int b_row = n0w + (sub >> 1) * 8 + rr;
    const int b_kof = (sub & 1) * 8;
    const int v_row = (sub & 1) * 8 + rr;
    const int v_col = (sub >> 1) * 8;

    const uint32_t uQh = sbase + OFF_QH, uQl = sbase + OFF_QL;
    const float gv = __ldg(&gate[h]);

    if (t < 128) l_buf[t] = 0.f;

    // ---- K/V async loader ----
    const size_t kvroot = (size_t)(b * N_) * THREEC_ + C_ + h * DH_;
    auto issue_kv = [&](int kt, int stage) {
        const size_t kbase = kvroot + (size_t)(kt * 128) * THREEC_;
        const uint32_t sb = sbase + OFF_KV + stage * AKV_STAGE;
        #pragma unroll
        for (int i = 0; i < 4; ++i) {
            const int idx = i * 256 + t;
            const int r   = idx >> 3;
            const int c8  = idx & 7;
            const size_t go = kbase + (size_t)r * THREEC_ + c8 * 8;
            const uint32_t so = sb + (uint32_t)(r * FPITCH + c8 * 8) * 2;
            CP_ASYNC16(so,               qkvh + go);
            CP_ASYNC16(so + FTILE_B,     qkvl + go);
            CP_ASYNC16(so + 2 * FTILE_B, qkvh + go + C_);
            CP_ASYNC16(so + 3 * FTILE_B, qkvl + go + C_);
        }
        CP_COMMIT();
    };

    // ---- Load Q tile (scaled by 0.125, exact in bf16) ----
    {
        const __nv_bfloat162 sc = __floats2bfloat162_rn(SCALE_, SCALE_);
        const size_t qbase = (size_t)(b * N_ + qt * 128) * THREEC_ + h * DH_;
        #pragma unroll
        for (int i = 0; i < 4; ++i) {
            const int idx = i * 256 + t;
            const int r   = idx >> 3;
            const int c8  = idx & 7;
            const size_t go = qbase + (size_t)r * THREEC_ + c8 * 8;
            union { int4 v; __nv_bfloat162 e[4]; } uh, ul;
            uh.v = *(const int4*)(qkvh + go);
            ul.v = *(const int4*)(qkvl + go);
            #pragma unroll
            for (int j = 0; j < 4; ++j) {
                uh.e[j] = __hmul2(uh.e[j], sc);
                ul.e[j] = __hmul2(ul.e[j], sc);
            }
            *(int4*)&Qh[r * FPITCH + c8 * 8] = uh.v;
            *(int4*)&Ql[r * FPITCH + c8 * 8] = ul.v;
        }
    }

    float oacc[2][8][4];
    #pragma unroll
    for (int mt = 0; mt < 2; ++mt)
        #pragma unroll
        for (int nt = 0; nt < 8; ++nt)
            #pragma unroll
            for (int i = 0; i < 4; ++i) oacc[mt][nt][i] = 0.f;
    float lsum[2][2] = {{0.f, 0.f}, {0.f, 0.f}};

    issue_kv(0, 0);

    for (int kt = 0; kt < N_ / 128; ++kt) {
        CP_WAIT0();
        __syncthreads();
        if (kt + 1 < N_ / 128) issue_kv(kt + 1, (kt + 1) & 1);

        const uint32_t sb  = sbase + OFF_KV + (kt & 1) * AKV_STAGE;
        const uint32_t uKh = sb;
        const uint32_t uKl = sb + FTILE_B;
        const uint32_t uVh = sb + 2 * FTILE_B;
        const uint32_t uVl = sb + 3 * FTILE_B;

        // ---- S = Q K^T (split-3, interleaved) ----
        float sacc[2][8][4];
        #pragma unroll
        for (int mt = 0; mt < 2; ++mt)
            #pragma unroll
            for (int nt = 0; nt < 8; ++nt)
                #pragma unroll
                for (int i = 0; i < 4; ++i) sacc[mt][nt][i] = 0.f;

        #pragma unroll
        for (int ks = 0; ks < 4; ++ks) {
            uint32_t ah[2][4], al[2][4], kbh[8][2], kbl[8][2];
            #pragma unroll
            for (int mt = 0; mt < 2; ++mt) {
                const uint32_t off = ((a_row + mt * 16) * FPITCH + ks * 16 + a_kof) * 2;
                ldsm_x4(ah[mt][0], ah[mt][1], ah[mt][2], ah[mt][3], uQh + off);
                ldsm_x4(al[mt][0], al[mt][1], al[mt][2], al[mt][3], uQl + off);
            }
            #pragma unroll
            for (int p = 0; p < 4; ++p) {
                const uint32_t off = ((b_row + p * 16) * FPITCH + ks * 16 + b_kof) * 2;
                uint32_t r0, r1, r2, r3;
                ldsm_x4(r0, r1, r2, r3, uKh + off);
                kbh[p * 2][0] = r0; kbh[p * 2][1] = r1;
                kbh[p * 2 + 1][0] = r2; kbh[p * 2 + 1][1] = r3;
                ldsm_x4(r0, r1, r2, r3, uKl + off);
                kbl[p * 2][0] = r0; kbl[p * 2][1] = r1;
                kbl[p * 2 + 1][0] = r2; kbl[p * 2 + 1][1] = r3;
            }
            #pragma unroll
            for (int mt = 0; mt < 2; ++mt)
                #pragma unroll
                for (int nt = 0; nt < 8; ++nt) {
                    mma_bf16(sacc[mt][nt], ah[mt], kbh[nt]);
                    mma_bf16(sacc[mt][nt], ah[mt], kbl[nt]);
                    mma_bf16(sacc[mt][nt], al[mt], kbh[nt]);
                }
        }

        // ---- softmax numerators + split P ----
        uint32_t phi01[2][8], phi23[2][8], plo01[2][8], plo23[2][8];
        #pragma unroll
        for (int mt = 0; mt < 2; ++mt)
            #pragma unroll
            for (int nt = 0; nt < 8; ++nt) {
                const float p0 = __expf(sacc[mt][nt][0]);
                const float p1 = __expf(sacc[mt][nt][1]);
                const float p2 = __expf(sacc[mt][nt][2]);
                const float p3 = __expf(sacc[mt][nt][3]);
                lsum[mt][0] += p0 + p1;
                lsum[mt][1] += p2 + p3;
                __nv_bfloat162 h01 = __floats2bfloat162_rn(p0, p1);
                __nv_bfloat162 h23 = __floats2bfloat162_rn(p2, p3);
                float2 f01 = __bfloat1622float2(h01);
                float2 f23 = __bfloat1622float2(h23);
                __nv_bfloat162 l01 = __floats2bfloat162_rn(p0 - f01.x, p1 - f01.y);
                __nv_bfloat162 l23 = __floats2bfloat162_rn(p2 - f23.x, p3 - f23.y);
                phi01[mt][nt] = *(uint32_t*)&h01;
                phi23[mt][nt] = *(uint32_t*)&h23;
                plo01[mt][nt] = *(uint32_t*)&l01;
                plo23[mt][nt] = *(uint32_t*)&l23;
            }

        // ---- O += P V (split-3, interleaved) ----
        #pragma unroll
        for (int ks = 0; ks < 4; ++ks) {
            uint32_t vbh[8][2], vbl[8][2];
            #pragma unroll
            for (int dp = 0; dp < 4; ++dp) {
                const uint32_t off = ((n0w + ks * 16 + v_row) * FPITCH + dp * 16 + v_col) * 2;
                uint32_t r0, r1, r2, r3;
                ldsm_x4_t(r0, r1, r2, r3, uVh + off);
                vbh[dp * 2][0] = r0; vbh[dp * 2][1] = r1;
                vbh[dp * 2 + 1][0] = r2; vbh[dp * 2 + 1][1] = r3;
                ldsm_x4_t(r0, r1, r2, r3, uVl + off);
                vbl[dp * 2][0] = r0; vbl[dp * 2][1] = r1;
                vbl[dp * 2 + 1][0] = r2; vbl[dp * 2 + 1][1] = r3;
            }
            #pragma unroll
            for (int mt = 0; mt < 2; ++mt) {
                const uint32_t pa_h[4] = { phi01[mt][2 * ks], phi23[mt][2 * ks],
                                           phi01[mt][2 * ks + 1], phi23[mt][2 * ks + 1] };
                const uint32_t pa_l[4] = { plo01[mt][2 * ks], plo23[mt][2 * ks],
                                           plo01[mt][2 * ks + 1], plo23[mt][2 * ks + 1] };
                #pragma unroll
                for (int nt = 0; nt < 8; ++nt) {
                    mma_bf16(oacc[mt][nt], pa_h, vbh[nt]);
                    mma_bf16(oacc[mt][nt], pa_h, vbl[nt]);
                    mma_bf16(oacc[mt][nt], pa_l, vbh[nt]);
                }
            }
        }
        // no bottom barrier: next iteration's CP_WAIT0 + __syncthreads orders
        // all readers of this stage before its buffer is re-issued (kt+2).
    }

    // ---- reduce l across tig quads and warp-pairs ----
    #pragma unroll
    for (int mt = 0; mt < 2; ++mt)
        #pragma unroll
        for (int half = 0; half < 2; ++half) {
            float v = lsum[mt][half];
            v += __shfl_xor_sync(0xFFFFFFFF, v, 1);
            v += __shfl_xor_sync(0xFFFFFFFF, v, 2);
            if (tig == 0)
                atomicAdd(&l_buf[m0w + mt * 16 + gid + half * 8], v);
        }
    __syncthreads();

    // ---- combine O across warp-pairs (staging overlays stage-0 K buffers) ----
    float* Obuf = (float*)(sm + OFF_KV);
    if (wid >= 4) {
        #pragma unroll
        for (int mt = 0; mt < 2; ++mt)
            #pragma unroll
            for (int nt = 0; nt < 8; ++nt) {
                const int row = m0w + mt * 16 + gid;
                const int col = nt * 8 + tig * 2;
                *(float2*)&Obuf[row * OPITCH + col] =
                    make_float2(oacc[mt][nt][0], oacc[mt][nt][1]);
                *(float2*)&Obuf[(row + 8) * OPITCH + col] =
                    make_float2(oacc[mt][nt][2], oacc[mt][nt][3]);
            }
    }
    __syncthreads();
    if (wid < 4) {
        #pragma unroll
        for (int mt = 0; mt < 2; ++mt) {
            const int row0l = m0w + mt * 16 + gid;
            const int row1l = row0l + 8;
            const float inv0 = gv / l_buf[row0l];
            const float inv1 = gv / l_buf[row1l];
            const size_t g0 = (size_t)(b * N_ + qt * 128 + row0l) * C_ + h * DH_;
            const size_t g1 = (size_t)(b * N_ + qt * 128 + row1l) * C_ + h * DH_;
            #pragma unroll
            for (int nt = 0; nt < 8; ++nt) {
                const int col = nt * 8 + tig * 2;
                const float o0 = (oacc[mt][nt][0] + Obuf[row0l * OPITCH + col])     * inv0;
                const float o1 = (oacc[mt][nt][1] + Obuf[row0l * OPITCH + col + 1]) * inv0;
                const float o2 = (oacc[mt][nt][2] + Obuf[row1l * OPITCH + col])     * inv1;
                const float o3 = (oacc[mt][nt][3] + Obuf[row1l * OPITCH + col + 1]) * inv1;
                __nv_bfloat162 h01 = __floats2bfloat162_rn(o0, o1);
                __nv_bfloat162 h23 = __floats2bfloat162_rn(o2, o3);
                float2 f01 = __bfloat1622float2(h01);
                float2 f23 = __bfloat1622float2(h23);
                __nv_bfloat162 l01 = __floats2bfloat162_rn(o0 - f01.x, o1 - f01.y);
                __nv_bfloat162 l23 = __floats2bfloat162_rn(o2 - f23.x, o3 - f23.y);
                *(__nv_bfloat162*)(atth + g0 + col) = h01;
                *(__nv_bfloat162*)(attl + g0 + col) = l01;
                *(__nv_bfloat162*)(atth + g1 + col) = h23;
                *(__nv_bfloat162*)(attl + g1 + col) = l23;
            }
        }
    }
}

// ---------------------------------------------------------------------------
// Launch
// ---------------------------------------------------------------------------
extern "C" void kernel_launch(void* const* d_in, const int* in_sizes, int n_in,
                              void* d_out, int out_size)
{
    const float* x      = (const float*)d_in[0];
    const float* w_qkv  = (const float*)d_in[1];
    const float* gate   = (const float*)d_in[2];
    const float* w_proj = (const float*)d_in[3];
    const float* b_proj = (const float*)d_in[4];
    float* out = (float*)d_out;

    __nv_bfloat16 *qkvh, *qkvl, *xh, *xl, *wqh, *wql, *wph, *wpl, *ath, *atl;
    cudaGetSymbolAddress((void**)&qkvh, g_qkvh);
    cudaGetSymbolAddress((void**)&qkvl, g_qkvl);
    cudaGetSymbolAddress((void**)&xh,   g_xh);
    cudaGetSymbolAddress((void**)&xl,   g_xl);
    cudaGetSymbolAddress((void**)&wqh,  g_wqkvTh);
    cudaGetSymbolAddress((void**)&wql,  g_wqkvTl);
    cudaGetSymbolAddress((void**)&wph,  g_wprojTh);
    cudaGetSymbolAddress((void**)&wpl,  g_wprojTl);
    cudaGetSymbolAddress((void**)&ath,  g_atth);
    cudaGetSymbolAddress((void**)&atl,  g_attl);

    cudaFuncSetAttribute(gemm_mma_kernel<128>,
                         cudaFuncAttributeMaxDynamicSharedMemorySize, G_SMEM_128);
    cudaFuncSetAttribute(gemm_mma_kernel<64>,
                         cudaFuncAttributeMaxDynamicSharedMemorySize, G_SMEM_64);
    cudaFuncSetAttribute(flash_attn_kernel,
                         cudaFuncAttributeMaxDynamicSharedMemorySize, ATTN_SMEM);

    // Prep: split x; transpose+split weights
    {
        int n = ROWS_ * C_;
        split_kernel<<<(n / 2 + 255) / 256, 256>>>(x, xh, xl, n);
        dim3 blk(32, 8);
        dim3 g1(THREEC_ / 32, C_ / 32);
        transpose_split_kernel<<<g1, blk>>>(w_qkv, wqh, wql, C_, THREEC_);
        dim3 g2(C_ / 32, C_ / 32);
        transpose_split_kernel<<<g2, blk>>>(w_proj, wph, wpl, C_, C_);
    }
    // 1) qkv = x @ w_qkv  -> split bf16 written directly by the epilogue
    {
        dim3 grid(THREEC_ / 128, ROWS_ / 128);
        gemm_mma_kernel<128><<<grid, 256, G_SMEM_128>>>(xh, xl, wqh, wql,
                                                        nullptr, nullptr, qkvh, qkvl,
                                                        ROWS_, THREEC_, C_);
    }
    // 2) flash attention + gate -> split bf16
    {
        dim3 grid(N_ / 128, B_ * H_);
        flash_attn_kernel<<<grid, 256, ATTN_SMEM>>>(qkvh, qkvl, gate, ath, atl);
    }
    // 3) out = att @ w_proj + b_proj  (fp32 epilogue, 128x64 tiles for tail)
    {
        dim3 grid(C_ / 64, ROWS_ / 128);
        gemm_mma_kernel<64><<<grid, 256, G_SMEM_64>>>(ath, atl, wph, wpl,
                                                      b_proj, out, nullptr, nullptr,
                                                      ROWS_, C_, C_);
    }
}